// round 1
// baseline (speedup 1.0000x reference)
#include <cuda_runtime.h>

// ---------------------------------------------------------------------------
// GNN message passing, 50000 nodes / 400000 edges / HIDDEN=256 / 3 layers.
//
// Factorization: concat([h[dst], h[src], e]) @ W1
//   = h[dst]@W1[0:256] + h[src]@W1[256:512] + e@W1[512:544]
// so the huge gathered edge-GEMM becomes two node GEMMs (Pa,Pb) + a cheap
// per-edge gather-add kernel. Remaining heavy GEMM (hidden1 @ W2) fuses the
// segment-sum scatter (atomicAdd) into its epilogue.
//
// Hcat[N,512] = [ h | aggr ] so the update MLP concat is a single K=512 GEMM.
// ---------------------------------------------------------------------------

#define NN 50000
#define NE 400000

// scratch (static __device__ arrays; no allocation in kernel_launch)
__device__ float g_Hcat[(size_t)NN * 512];   // [h | aggr]
__device__ float g_P[(size_t)NN * 512];      // [Pa | Pb]
__device__ float g_M1[(size_t)NE * 256];     // hidden1 per edge
__device__ float g_U[(size_t)NN * 256];      // update MLP hidden
__device__ float g_E[(size_t)NE * 32];       // projected edge features
__device__ float g_T[(size_t)NN * 128];      // token head hidden

// ---------------------------------------------------------------------------
// Generic 128x128x8 SGEMM, 256 threads, 8x8 per thread, float4 everywhere.
// C[M,N] = act(A[M,K]@B[K,N] + bias). Optional fused atomic scatter epilogue:
// atomicAdd(C[sidx[row]*ldc + col], v) instead of direct store.
// Requires: K % 8 == 0, N % 128 == 0, lda/ldb/ldc % 4 == 0. M is guarded.
// ---------------------------------------------------------------------------
template <bool RELU, bool SCATTER>
__global__ __launch_bounds__(256) void sgemm(
    const float* __restrict__ A, int lda,
    const float* __restrict__ B, int ldb,
    const float* __restrict__ bias,
    float* __restrict__ C, int ldc,
    int M, int N, int K,
    const int* __restrict__ sidx)
{
    __shared__ float As[8][128];
    __shared__ float Bs[8][128];

    const int tid  = threadIdx.x;
    const int row0 = blockIdx.y * 128;
    const int col0 = blockIdx.x * 128;

    const int arow = tid >> 1;
    const int acol = (tid & 1) << 2;
    const int brow = tid >> 5;
    const int bcol = (tid & 31) << 2;

    const float* Ap = A + (size_t)(row0 + arow) * lda + acol;
    const float* Bp = B + (size_t)brow * ldb + col0 + bcol;
    const bool aok = (row0 + arow) < M;

    const int tr = (tid >> 4) << 3;
    const int tc = (tid & 15) << 3;

    float acc[8][8];
#pragma unroll
    for (int i = 0; i < 8; i++)
#pragma unroll
        for (int j = 0; j < 8; j++) acc[i][j] = 0.f;

    for (int k0 = 0; k0 < K; k0 += 8) {
        float4 av = aok ? *(const float4*)Ap : make_float4(0.f, 0.f, 0.f, 0.f);
        float4 bv = *(const float4*)Bp;
        __syncthreads();
        As[acol + 0][arow] = av.x;
        As[acol + 1][arow] = av.y;
        As[acol + 2][arow] = av.z;
        As[acol + 3][arow] = av.w;
        *(float4*)&Bs[brow][bcol] = bv;
        __syncthreads();
#pragma unroll
        for (int k = 0; k < 8; k++) {
            float a[8], b[8];
            *(float4*)(a)     = *(const float4*)&As[k][tr];
            *(float4*)(a + 4) = *(const float4*)&As[k][tr + 4];
            *(float4*)(b)     = *(const float4*)&Bs[k][tc];
            *(float4*)(b + 4) = *(const float4*)&Bs[k][tc + 4];
#pragma unroll
            for (int i = 0; i < 8; i++)
#pragma unroll
                for (int j = 0; j < 8; j++)
                    acc[i][j] = fmaf(a[i], b[j], acc[i][j]);
        }
        Ap += 8;
        Bp += (size_t)8 * ldb;
    }

#pragma unroll
    for (int i = 0; i < 8; i++) {
        int r = row0 + tr + i;
        if (r >= M) continue;
        if (SCATTER) {
            int target = sidx[r];
            float* Crow = C + (size_t)target * ldc + col0 + tc;
#pragma unroll
            for (int j = 0; j < 8; j++) {
                float v = acc[i][j] + bias[col0 + tc + j];
                if (RELU) v = fmaxf(v, 0.f);
                atomicAdd(Crow + j, v);
            }
        } else {
            float* Crow = C + (size_t)r * ldc + col0 + tc;
            float4 o0, o1;
            float v[8];
#pragma unroll
            for (int j = 0; j < 8; j++) {
                v[j] = acc[i][j] + (bias ? bias[col0 + tc + j] : 0.f);
                if (RELU) v[j] = fmaxf(v[j], 0.f);
            }
            o0 = make_float4(v[0], v[1], v[2], v[3]);
            o1 = make_float4(v[4], v[5], v[6], v[7]);
            *(float4*)(Crow)     = o0;
            *(float4*)(Crow + 4) = o1;
        }
    }
}

// ---------------------------------------------------------------------------
// hidden1[e, :] = relu( Pa[dst[e]] + Pb[src[e]] + ebuf[e]·Wc + b1 )
// 256 threads (one per output column), 16 edges per block.
// ---------------------------------------------------------------------------
#define ET 16
__global__ __launch_bounds__(256) void hidden1_kernel(
    const float* __restrict__ P,    // [N, 512] = [Pa | Pb]
    const float* __restrict__ Ebuf, // [E, 32]
    const float* __restrict__ Wc,   // [32, 256]
    const float* __restrict__ b1,   // [256]
    const int* __restrict__ src,
    const int* __restrict__ dst,
    float* __restrict__ out,        // [E, 256]
    int E)
{
    const int j = threadIdx.x;
    const int e0 = blockIdx.x * ET;
    __shared__ float esm[ET][32];
    __shared__ int sdst[ET], ssrc[ET];

    float wc[32];
#pragma unroll
    for (int k = 0; k < 32; k++) wc[k] = Wc[k * 256 + j];

    const int ne = min(ET, E - e0);
    if (j < ne) {
        sdst[j] = dst[e0 + j];
        ssrc[j] = src[e0 + j];
    }
    for (int t = j; t < ne * 32; t += 256)
        esm[t >> 5][t & 31] = Ebuf[(size_t)e0 * 32 + t];
    __syncthreads();

    const float bj = b1[j];
    for (int i = 0; i < ne; i++) {
        float acc = bj + P[(size_t)sdst[i] * 512 + j]
                       + P[(size_t)ssrc[i] * 512 + 256 + j];
#pragma unroll
        for (int k = 0; k < 32; k++) acc = fmaf(esm[i][k], wc[k], acc);
        out[(size_t)(e0 + i) * 256 + j] = fmaxf(acc, 0.f);
    }
}

// ---------------------------------------------------------------------------
// edge projection: out[E,32] = ea[E,32] @ W[32,32] + b  (8 edges per block)
// ---------------------------------------------------------------------------
__global__ __launch_bounds__(256) void edge_proj(
    const float* __restrict__ ea, const float* __restrict__ W,
    const float* __restrict__ b, float* __restrict__ out, int E)
{
    __shared__ float Ws[1024];
    __shared__ float es[8][32];
    const int t = threadIdx.x;
    for (int i = t; i < 1024; i += 256) Ws[i] = W[i];
    const int e0 = blockIdx.x * 8;
    const int ne = min(8, E - e0);
    for (int i = t; i < ne * 32; i += 256)
        es[i >> 5][i & 31] = ea[(size_t)e0 * 32 + i];
    __syncthreads();
    const int el = t >> 5, c = t & 31;
    if (el < ne) {
        float acc = b[c];
#pragma unroll
        for (int k = 0; k < 32; k++) acc = fmaf(es[el][k], Ws[k * 32 + c], acc);
        out[(size_t)(e0 + el) * 32 + c] = acc;
    }
}

// zero the aggr half of Hcat (cols 256..511)
__global__ void zero_aggr(float* __restrict__ Hcat, int N)
{
    int idx = blockIdx.x * blockDim.x + threadIdx.x;
    if (idx < N * 64) {
        int r = idx >> 6, c = (idx & 63) << 2;
        *(float4*)(Hcat + (size_t)r * 512 + 256 + c) = make_float4(0.f, 0.f, 0.f, 0.f);
    }
}

// logits[row] = T[row,:128]·w2 + b2   (one warp per row)
__global__ void head2(const float* __restrict__ T, const float* __restrict__ w2,
                      const float* __restrict__ b2, float* __restrict__ out, int N)
{
    int gw = (blockIdx.x * blockDim.x + threadIdx.x) >> 5;
    int lane = threadIdx.x & 31;
    if (gw >= N) return;
    const float* row = T + (size_t)gw * 128;
    float s = 0.f;
#pragma unroll
    for (int k = lane; k < 128; k += 32) s = fmaf(row[k], w2[k], s);
#pragma unroll
    for (int o = 16; o; o >>= 1) s += __shfl_xor_sync(0xFFFFFFFFu, s, o);
    if (lane == 0) out[gw] = s + b2[0];
}

// copy h (cols 0..255 of Hcat) into the output tensor
__global__ void copy_h(const float* __restrict__ Hcat, float* __restrict__ out, int N)
{
    int idx = blockIdx.x * blockDim.x + threadIdx.x;
    if (idx < N * 64) {
        int r = idx >> 6, c = (idx & 63) << 2;
        *(float4*)(out + (size_t)r * 256 + c) =
            *(const float4*)(Hcat + (size_t)r * 512 + c);
    }
}

// ---------------------------------------------------------------------------
extern "C" void kernel_launch(void* const* d_in, const int* in_sizes, int n_in,
                              void* d_out, int out_size)
{
    const float* x       = (const float*)d_in[0];
    const int*   ei      = (const int*)d_in[1];
    const float* ea      = (const float*)d_in[2];
    const float* node_w  = (const float*)d_in[3];
    const float* node_b  = (const float*)d_in[4];
    const float* edge_w  = (const float*)d_in[5];
    const float* edge_b  = (const float*)d_in[6];
    const float* msg_w1  = (const float*)d_in[7];
    const float* msg_b1  = (const float*)d_in[8];
    const float* msg_w2  = (const float*)d_in[9];
    const float* msg_b2  = (const float*)d_in[10];
    const float* up_w1   = (const float*)d_in[11];
    const float* up_b1   = (const float*)d_in[12];
    const float* up_w2   = (const float*)d_in[13];
    const float* up_b2   = (const float*)d_in[14];
    const float* tok_w1  = (const float*)d_in[15];
    const float* tok_b1  = (const float*)d_in[16];
    const float* tok_w2  = (const float*)d_in[17];
    const float* tok_b2  = (const float*)d_in[18];

    const int N = in_sizes[0] / 128;   // 50000
    const int E = in_sizes[2] / 32;    // 400000
    const int* src = ei;               // edge_index[0]
    const int* dst = ei + E;           // edge_index[1]

    float *Hcat, *P, *M1, *U, *Eb, *T;
    cudaGetSymbolAddress((void**)&Hcat, g_Hcat);
    cudaGetSymbolAddress((void**)&P,    g_P);
    cudaGetSymbolAddress((void**)&M1,   g_M1);
    cudaGetSymbolAddress((void**)&U,    g_U);
    cudaGetSymbolAddress((void**)&Eb,   g_E);
    cudaGetSymbolAddress((void**)&T,    g_T);

    float* out_logits = (float*)d_out;
    float* out_h      = out_logits + N;

    const int mbN = (N + 127) / 128;   // 391
    const int mbE = (E + 127) / 128;   // 3125

    // h = x @ node_w + node_b  -> Hcat[:, 0:256]
    sgemm<false, false><<<dim3(2, mbN), 256>>>(x, 128, node_w, 256, node_b,
                                               Hcat, 512, N, 256, 128, nullptr);
    // e = edge_attr @ edge_w + edge_b
    edge_proj<<<(E + 7) / 8, 256>>>(ea, edge_w, edge_b, Eb, E);

    for (int l = 0; l < 3; l++) {
        const float* w1 = msg_w1 + (size_t)l * 544 * 256;
        // Pa = h @ W1[0:256], Pb = h @ W1[256:512]
        sgemm<false, false><<<dim3(2, mbN), 256>>>(Hcat, 512, w1, 256, nullptr,
                                                   P, 512, N, 256, 256, nullptr);
        sgemm<false, false><<<dim3(2, mbN), 256>>>(Hcat, 512, w1 + 256 * 256, 256, nullptr,
                                                   P + 256, 512, N, 256, 256, nullptr);
        // aggr = 0
        zero_aggr<<<(N * 64 + 255) / 256, 256>>>(Hcat, N);
        // hidden1 = relu(Pa[dst] + Pb[src] + e@Wc + b1)
        hidden1_kernel<<<(E + ET - 1) / ET, 256>>>(P, Eb, w1 + 512 * 256,
                                                   msg_b1 + l * 256, src, dst, M1, E);
        // m = relu(hidden1 @ W2 + b2); aggr[dst] += m   (fused scatter)
        sgemm<true, true><<<dim3(2, mbE), 256>>>(M1, 256,
                                                 msg_w2 + (size_t)l * 256 * 256, 256,
                                                 msg_b2 + l * 256,
                                                 Hcat + 256, 512, E, 256, 256, dst);
        // u = relu([h|aggr] @ up_w1 + b1)
        sgemm<true, false><<<dim3(2, mbN), 256>>>(Hcat, 512,
                                                  up_w1 + (size_t)l * 512 * 256, 256,
                                                  up_b1 + l * 256,
                                                  U, 256, N, 256, 512, nullptr);
        // h = relu(u @ up_w2 + b2) -> Hcat[:, 0:256]
        sgemm<true, false><<<dim3(2, mbN), 256>>>(U, 256,
                                                  up_w2 + (size_t)l * 256 * 256, 256,
                                                  up_b2 + l * 256,
                                                  Hcat, 512, N, 256, 256, nullptr);
    }

    // token head
    sgemm<true, false><<<dim3(1, mbN), 256>>>(Hcat, 512, tok_w1, 128, tok_b1,
                                              T, 128, N, 128, 256, nullptr);
    head2<<<(N * 32 + 255) / 256, 256>>>(T, tok_w2, tok_b2, out_logits, N);
    copy_h<<<(N * 64 + 255) / 256, 256>>>(Hcat, out_h, N);
}

// round 3
// speedup vs baseline: 2.1055x; 2.1055x over previous
#include <cuda_runtime.h>

// ---------------------------------------------------------------------------
// GNN message passing, 50000 nodes / 400000 edges / HIDDEN=256 / 3 layers.
// All GEMMs run on tensor cores via tf32 mma.sync.m16n8k8 (fp32 accum).
//
// Factorization: concat([h[dst], h[src], e]) @ W1
//   = h[dst]@W1[0:256] + h[src]@W1[256:512] + e@W1[512:544]
// Hcat[N,512] = [ h | aggr ] so the update MLP concat is a single K=512 GEMM.
// Segment-sum scatter fused into the edge GEMM epilogue (atomicAdd -> REDG).
// ---------------------------------------------------------------------------

#define NN 50000
#define NE 400000

__device__ float g_Hcat[(size_t)NN * 512];   // [h | aggr]
__device__ float g_P[(size_t)NN * 512];      // [Pa | Pb]
__device__ float g_M1[(size_t)NE * 256];     // hidden1 per edge
__device__ float g_U[(size_t)NN * 256];      // update MLP hidden
__device__ float g_E[(size_t)NE * 32];       // projected edge features
__device__ float g_T[(size_t)NN * 128];      // token head hidden

__device__ __forceinline__ unsigned f2tf(float f) {
    unsigned u;
    asm("cvt.rna.tf32.f32 %0, %1;" : "=r"(u) : "f"(f));
    return u;
}

// ---------------------------------------------------------------------------
// TF32 tensor-core GEMM: C[M,N] = act(A[M,K] @ B[K,N] + bias)
// 128x128 CTA tile, BK=16, 256 threads (8 warps of 32x64), double-buffered.
// SCATTER: atomicAdd into C[sidx[row]] instead of store.
// Requires K%16==0, N%128==0 per grid (gridDim.x covers N/128).
// ---------------------------------------------------------------------------
template <bool RELU, bool SCATTER>
__global__ __launch_bounds__(256) void tf32gemm(
    const float* __restrict__ A, int lda,
    const float* __restrict__ B, int ldb,
    const float* __restrict__ bias,
    float* __restrict__ C, int ldc,
    int M, int N, int K,
    const int* __restrict__ sidx)
{
    __shared__ unsigned As[2][128][20];   // m-major, stride 20 (a-frag conflict-free)
    __shared__ unsigned Bs[2][16][136];   // k-major, stride 136 (b-frag conflict-free)

    const int tid  = threadIdx.x;
    const int lane = tid & 31;
    const int wid  = tid >> 5;
    const int warpRow = wid >> 1;          // 0..3  (32 rows each)
    const int warpCol = wid & 1;           // 0..1  (64 cols each)
    const int qr = lane >> 2;              // 0..7
    const int qk = lane & 3;               // 0..3

    const int row0 = blockIdx.y * 128;
    const int col0 = blockIdx.x * 128;

    // --- staging assignment ---
    // A: idx in [0,512): row=idx>>2, c4=idx&3 -> float4 at A[row0+row][k0+c4*4]
    // B: idx in [0,512): k=idx>>5,  c4=idx&31 -> float4 at B[k0+k][col0+c4*4]
    const int aRow0 = tid >> 2;            // thread's first A row
    const int aC4   = tid & 3;
    const int bK0   = tid >> 5;
    const int bC4   = tid & 31;

    float4 aReg[2], bReg[2];

    auto loadA = [&](int k0, float4* r) {
#pragma unroll
        for (int u = 0; u < 2; u++) {
            int row = aRow0 + u * 64;
            if (row0 + row < M)
                r[u] = *(const float4*)(A + (size_t)(row0 + row) * lda + k0 + aC4 * 4);
            else
                r[u] = make_float4(0.f, 0.f, 0.f, 0.f);
        }
    };
    auto loadB = [&](int k0, float4* r) {
#pragma unroll
        for (int u = 0; u < 2; u++) {
            int k = bK0 + u * 8;
            r[u] = *(const float4*)(B + (size_t)(k0 + k) * ldb + col0 + bC4 * 4);
        }
    };
    auto stage = [&](int st, const float4* ra, const float4* rb) {
#pragma unroll
        for (int u = 0; u < 2; u++) {
            int row = aRow0 + u * 64;
            unsigned* p = &As[st][row][aC4 * 4];
            p[0] = f2tf(ra[u].x); p[1] = f2tf(ra[u].y);
            p[2] = f2tf(ra[u].z); p[3] = f2tf(ra[u].w);
        }
#pragma unroll
        for (int u = 0; u < 2; u++) {
            int k = bK0 + u * 8;
            unsigned* p = &Bs[st][k][bC4 * 4];
            p[0] = f2tf(rb[u].x); p[1] = f2tf(rb[u].y);
            p[2] = f2tf(rb[u].z); p[3] = f2tf(rb[u].w);
        }
    };

    float acc[2][8][4];
#pragma unroll
    for (int i = 0; i < 2; i++)
#pragma unroll
        for (int j = 0; j < 8; j++)
#pragma unroll
            for (int c = 0; c < 4; c++) acc[i][j][c] = 0.f;

    const int mbase = warpRow * 32;
    const int nbase = warpCol * 64;

    loadA(0, aReg); loadB(0, bReg);
    stage(0, aReg, bReg);
    __syncthreads();

    const int stages = K >> 4;
    for (int s = 0; s < stages; s++) {
        const int cur = s & 1;
        if (s + 1 < stages) { loadA((s + 1) << 4, aReg); loadB((s + 1) << 4, bReg); }

#pragma unroll
        for (int kk = 0; kk < 16; kk += 8) {
            unsigned a[2][4], b[8][2];
#pragma unroll
            for (int i = 0; i < 2; i++) {
                int r = mbase + i * 16 + qr;
                a[i][0] = As[cur][r][kk + qk];
                a[i][1] = As[cur][r + 8][kk + qk];
                a[i][2] = As[cur][r][kk + 4 + qk];
                a[i][3] = As[cur][r + 8][kk + 4 + qk];
            }
#pragma unroll
            for (int j = 0; j < 8; j++) {
                int c = nbase + j * 8 + qr;
                b[j][0] = Bs[cur][kk + qk][c];
                b[j][1] = Bs[cur][kk + 4 + qk][c];
            }
#pragma unroll
            for (int i = 0; i < 2; i++)
#pragma unroll
                for (int j = 0; j < 8; j++) {
                    asm volatile(
                        "mma.sync.aligned.m16n8k8.row.col.f32.tf32.tf32.f32 "
                        "{%0,%1,%2,%3}, {%4,%5,%6,%7}, {%8,%9}, {%0,%1,%2,%3};"
                        : "+f"(acc[i][j][0]), "+f"(acc[i][j][1]),
                          "+f"(acc[i][j][2]), "+f"(acc[i][j][3])
                        : "r"(a[i][0]), "r"(a[i][1]), "r"(a[i][2]), "r"(a[i][3]),
                          "r"(b[j][0]), "r"(b[j][1]));
                }
        }

        if (s + 1 < stages) stage(cur ^ 1, aReg, bReg);
        __syncthreads();
    }

    // epilogue: c0,c1 at (qr, 2qk), c2,c3 at (qr+8, 2qk) within each 16x8 tile
#pragma unroll
    for (int i = 0; i < 2; i++) {
#pragma unroll
        for (int h = 0; h < 2; h++) {   // h=0: rows qr, h=1: rows qr+8
            int r = row0 + mbase + i * 16 + qr + h * 8;
            if (r >= M) continue;
            if (SCATTER) {
                int target = sidx[r];
                float* Crow = C + (size_t)target * ldc;
#pragma unroll
                for (int j = 0; j < 8; j++) {
                    int c = col0 + nbase + j * 8 + 2 * qk;
                    float v0 = acc[i][j][h * 2 + 0] + bias[c];
                    float v1 = acc[i][j][h * 2 + 1] + bias[c + 1];
                    if (RELU) { v0 = fmaxf(v0, 0.f); v1 = fmaxf(v1, 0.f); }
                    atomicAdd(Crow + c, v0);
                    atomicAdd(Crow + c + 1, v1);
                }
            } else {
                float* Crow = C + (size_t)r * ldc;
#pragma unroll
                for (int j = 0; j < 8; j++) {
                    int c = col0 + nbase + j * 8 + 2 * qk;
                    float v0 = acc[i][j][h * 2 + 0] + (bias ? bias[c] : 0.f);
                    float v1 = acc[i][j][h * 2 + 1] + (bias ? bias[c + 1] : 0.f);
                    if (RELU) { v0 = fmaxf(v0, 0.f); v1 = fmaxf(v1, 0.f); }
                    *(float2*)(Crow + c) = make_float2(v0, v1);
                }
            }
        }
    }
}

// ---------------------------------------------------------------------------
// hidden1[e, :] = relu( Pa[dst[e]] + Pb[src[e]] + ebuf[e]·Wc + b1 )
// ---------------------------------------------------------------------------
#define ET 16
__global__ __launch_bounds__(256) void hidden1_kernel(
    const float* __restrict__ P,    // [N, 512] = [Pa | Pb]
    const float* __restrict__ Ebuf, // [E, 32]
    const float* __restrict__ Wc,   // [32, 256]
    const float* __restrict__ b1,   // [256]
    const int* __restrict__ src,
    const int* __restrict__ dst,
    float* __restrict__ out,        // [E, 256]
    int E)
{
    const int j = threadIdx.x;
    const int e0 = blockIdx.x * ET;
    __shared__ float esm[ET][32];
    __shared__ int sdst[ET], ssrc[ET];

    float wc[32];
#pragma unroll
    for (int k = 0; k < 32; k++) wc[k] = Wc[k * 256 + j];

    const int ne = min(ET, E - e0);
    if (j < ne) {
        sdst[j] = dst[e0 + j];
        ssrc[j] = src[e0 + j];
    }
    for (int t = j; t < ne * 32; t += 256)
        esm[t >> 5][t & 31] = Ebuf[(size_t)e0 * 32 + t];
    __syncthreads();

    const float bj = b1[j];
    for (int i = 0; i < ne; i++) {
        float acc = bj + P[(size_t)sdst[i] * 512 + j]
                       + P[(size_t)ssrc[i] * 512 + 256 + j];
#pragma unroll
        for (int k = 0; k < 32; k++) acc = fmaf(esm[i][k], wc[k], acc);
        out[(size_t)(e0 + i) * 256 + j] = fmaxf(acc, 0.f);
    }
}

// ---------------------------------------------------------------------------
__global__ __launch_bounds__(256) void edge_proj(
    const float* __restrict__ ea, const float* __restrict__ W,
    const float* __restrict__ b, float* __restrict__ out, int E)
{
    __shared__ float Ws[1024];
    __shared__ float es[8][32];
    const int t = threadIdx.x;
    for (int i = t; i < 1024; i += 256) Ws[i] = W[i];
    const int e0 = blockIdx.x * 8;
    const int ne = min(8, E - e0);
    for (int i = t; i < ne * 32; i += 256)
        es[i >> 5][i & 31] = ea[(size_t)e0 * 32 + i];
    __syncthreads();
    const int el = t >> 5, c = t & 31;
    if (el < ne) {
        float acc = b[c];
#pragma unroll
        for (int k = 0; k < 32; k++) acc = fmaf(es[el][k], Ws[k * 32 + c], acc);
        out[(size_t)(e0 + el) * 32 + c] = acc;
    }
}

__global__ void zero_aggr(float* __restrict__ Hcat, int N)
{
    int idx = blockIdx.x * blockDim.x + threadIdx.x;
    if (idx < N * 64) {
        int r = idx >> 6, c = (idx & 63) << 2;
        *(float4*)(Hcat + (size_t)r * 512 + 256 + c) = make_float4(0.f, 0.f, 0.f, 0.f);
    }
}

__global__ void head2(const float* __restrict__ T, const float* __restrict__ w2,
                      const float* __restrict__ b2, float* __restrict__ out, int N)
{
    int gw = (blockIdx.x * blockDim.x + threadIdx.x) >> 5;
    int lane = threadIdx.x & 31;
    if (gw >= N) return;
    const float* row = T + (size_t)gw * 128;
    float s = 0.f;
#pragma unroll
    for (int k = lane; k < 128; k += 32) s = fmaf(row[k], w2[k], s);
#pragma unroll
    for (int o = 16; o; o >>= 1) s += __shfl_xor_sync(0xFFFFFFFFu, s, o);
    if (lane == 0) out[gw] = s + b2[0];
}

__global__ void copy_h(const float* __restrict__ Hcat, float* __restrict__ out, int N)
{
    int idx = blockIdx.x * blockDim.x + threadIdx.x;
    if (idx < N * 64) {
        int r = idx >> 6, c = (idx & 63) << 2;
        *(float4*)(out + (size_t)r * 256 + c) =
            *(const float4*)(Hcat + (size_t)r * 512 + c);
    }
}

// ---------------------------------------------------------------------------
extern "C" void kernel_launch(void* const* d_in, const int* in_sizes, int n_in,
                              void* d_out, int out_size)
{
    const float* x       = (const float*)d_in[0];
    const int*   ei      = (const int*)d_in[1];
    const float* ea      = (const float*)d_in[2];
    const float* node_w  = (const float*)d_in[3];
    const float* node_b  = (const float*)d_in[4];
    const float* edge_w  = (const float*)d_in[5];
    const float* edge_b  = (const float*)d_in[6];
    const float* msg_w1  = (const float*)d_in[7];
    const float* msg_b1  = (const float*)d_in[8];
    const float* msg_w2  = (const float*)d_in[9];
    const float* msg_b2  = (const float*)d_in[10];
    const float* up_w1   = (const float*)d_in[11];
    const float* up_b1   = (const float*)d_in[12];
    const float* up_w2   = (const float*)d_in[13];
    const float* up_b2   = (const float*)d_in[14];
    const float* tok_w1  = (const float*)d_in[15];
    const float* tok_b1  = (const float*)d_in[16];
    const float* tok_w2  = (const float*)d_in[17];
    const float* tok_b2  = (const float*)d_in[18];

    const int N = in_sizes[0] / 128;   // 50000
    const int E = in_sizes[2] / 32;    // 400000
    const int* src = ei;               // edge_index[0]
    const int* dst = ei + E;           // edge_index[1]

    float *Hcat, *P, *M1, *U, *Eb, *T;
    cudaGetSymbolAddress((void**)&Hcat, g_Hcat);
    cudaGetSymbolAddress((void**)&P,    g_P);
    cudaGetSymbolAddress((void**)&M1,   g_M1);
    cudaGetSymbolAddress((void**)&U,    g_U);
    cudaGetSymbolAddress((void**)&Eb,   g_E);
    cudaGetSymbolAddress((void**)&T,    g_T);

    float* out_logits = (float*)d_out;
    float* out_h      = out_logits + N;

    const int mbN = (N + 127) / 128;   // 391
    const int mbE = (E + 127) / 128;   // 3125

    // h = x @ node_w + node_b  -> Hcat[:, 0:256]
    tf32gemm<false, false><<<dim3(2, mbN), 256>>>(x, 128, node_w, 256, node_b,
                                                  Hcat, 512, N, 256, 128, nullptr);
    // e = edge_attr @ edge_w + edge_b
    edge_proj<<<(E + 7) / 8, 256>>>(ea, edge_w, edge_b, Eb, E);

    for (int l = 0; l < 3; l++) {
        const float* w1 = msg_w1 + (size_t)l * 544 * 256;
        // Pa = h @ W1[0:256], Pb = h @ W1[256:512]
        tf32gemm<false, false><<<dim3(2, mbN), 256>>>(Hcat, 512, w1, 256, nullptr,
                                                      P, 512, N, 256, 256, nullptr);
        tf32gemm<false, false><<<dim3(2, mbN), 256>>>(Hcat, 512, w1 + 256 * 256, 256, nullptr,
                                                      P + 256, 512, N, 256, 256, nullptr);
        // aggr = 0
        zero_aggr<<<(N * 64 + 255) / 256, 256>>>(Hcat, N);
        // hidden1 = relu(Pa[dst] + Pb[src] + e@Wc + b1)
        hidden1_kernel<<<(E + ET - 1) / ET, 256>>>(P, Eb, w1 + 512 * 256,
                                                   msg_b1 + l * 256, src, dst, M1, E);
        // m = relu(hidden1 @ W2 + b2); aggr[dst] += m   (fused scatter)
        tf32gemm<true, true><<<dim3(2, mbE), 256>>>(M1, 256,
                                                    msg_w2 + (size_t)l * 256 * 256, 256,
                                                    msg_b2 + l * 256,
                                                    Hcat + 256, 512, E, 256, 256, dst);
        // u = relu([h|aggr] @ up_w1 + b1)
        tf32gemm<true, false><<<dim3(2, mbN), 256>>>(Hcat, 512,
                                                     up_w1 + (size_t)l * 512 * 256, 256,
                                                     up_b1 + l * 256,
                                                     U, 256, N, 256, 512, nullptr);
        // h = relu(u @ up_w2 + b2) -> Hcat[:, 0:256]
        tf32gemm<true, false><<<dim3(2, mbN), 256>>>(U, 256,
                                                     up_w2 + (size_t)l * 256 * 256, 256,
                                                     up_b2 + l * 256,
                                                     Hcat, 512, N, 256, 256, nullptr);
    }

    // token head
    tf32gemm<true, false><<<dim3(1, mbN), 256>>>(Hcat, 512, tok_w1, 128, tok_b1,
                                                 T, 128, N, 128, 256, nullptr);
    head2<<<(N * 32 + 255) / 256, 256>>>(T, tok_w2, tok_b2, out_logits, N);
    copy_h<<<(N * 64 + 255) / 256, 256>>>(Hcat, out_h, N);
}

// round 5
// speedup vs baseline: 2.1580x; 1.0249x over previous
#include <cuda_runtime.h>
#include <cstdint>

// ---------------------------------------------------------------------------
// GNN message passing, 50000 nodes / 400000 edges / HIDDEN=256 / 3 layers.
// GEMMs via tf32 mma.sync.m16n8k8 (sm_100 has no tcgen05 in this toolchain).
//
// Factorization: concat([h[dst], h[src], e]) @ W1
//   = h[dst]@W1[0:256] + h[src]@W1[256:512] + e@W1[512:544]
// Hcat[N,512] = [ h | aggr ]; update MLP concat = single K=512 GEMM.
// Segment-sum scatter fused into edge GEMM epilogue (red.global.add.v2.f32).
// A-fragments read via conflict-free LDS.64 pair layout (stride-68 + XOR).
// ---------------------------------------------------------------------------

#define NN 50000
#define NE 400000

__device__ float g_Hcat[(size_t)NN * 512];   // [h | aggr]
__device__ float g_P[(size_t)NN * 512];      // [Pa | Pb]
__device__ float g_M1[(size_t)NE * 256];     // hidden1 per edge
__device__ float g_U[(size_t)NN * 256];      // update MLP hidden
__device__ float g_E[(size_t)NE * 32];       // projected edge features
__device__ float g_T[(size_t)NN * 128];      // token head hidden

__device__ __forceinline__ unsigned f2tf(float f) {
    unsigned u;
    asm("cvt.rna.tf32.f32 %0, %1;" : "=r"(u) : "f"(f));
    return u;
}

// ---------------------------------------------------------------------------
// TF32 tensor-core GEMM: C[M,N] = act(A[M,K] @ B[K,N] + bias)
// 128x128 CTA tile, BK=16, 256 threads (8 warps of 32x64), double-buffered.
// A-frags: uint2 pair layout, LDS.64 conflict-free.
// B-frags: scalar layout Bs[16][136] (proven conflict-free).
// SCATTER: red.add.v2 into C[sidx[row]] instead of store.
// ---------------------------------------------------------------------------
template <bool RELU, bool SCATTER>
__global__ __launch_bounds__(256, 2) void tf32gemm(
    const float* __restrict__ A, int lda,
    const float* __restrict__ B, int ldb,
    const float* __restrict__ bias,
    float* __restrict__ C, int ldc,
    int M, int N, int K,
    const int* __restrict__ sidx)
{
    // A pair layout (uint2): idx = kkb*544 + s*272 + (qk^c4)*68 + rr
    //   where c4 = kkb*2+s, rr = (r>>4)*8 + (r&7), pair component = (r>>3)&1
    __shared__ uint2 Apair[2][1088];
    __shared__ unsigned Bs[2][16][136];

    const int tid  = threadIdx.x;
    const int lane = tid & 31;
    const int wid  = tid >> 5;
    const int warpRow = wid >> 1;          // 0..3  (32 rows each)
    const int warpCol = wid & 1;           // 0..1  (64 cols each)
    const int qr = lane >> 2;              // 0..7
    const int qk = lane & 3;               // 0..3

    const int row0 = blockIdx.y * 128;
    const int col0 = blockIdx.x * 128;

    const int aRow0 = tid >> 2;            // thread's first A row
    const int aC4   = tid & 3;
    const int bK0   = tid >> 5;
    const int bC4   = tid & 31;

    float4 aReg[2], bReg[2];

    auto loadA = [&](int k0, float4* r) {
#pragma unroll
        for (int u = 0; u < 2; u++) {
            int row = aRow0 + u * 64;
            if (row0 + row < M)
                r[u] = *(const float4*)(A + (size_t)(row0 + row) * lda + k0 + aC4 * 4);
            else
                r[u] = make_float4(0.f, 0.f, 0.f, 0.f);
        }
    };
    auto loadB = [&](int k0, float4* r) {
#pragma unroll
        for (int u = 0; u < 2; u++) {
            int k = bK0 + u * 8;
            r[u] = *(const float4*)(B + (size_t)(k0 + k) * ldb + col0 + bC4 * 4);
        }
    };
    auto stage = [&](int st, const float4* ra, const float4* rb) {
        unsigned* abase = (unsigned*)&Apair[st][0];
        const int kkb = aC4 >> 1, s = aC4 & 1;
#pragma unroll
        for (int u = 0; u < 2; u++) {
            int r = aRow0 + u * 64;
            int h = (r >> 3) & 1;
            int rr = ((r >> 4) << 3) | (r & 7);
            int bi = kkb * 544 + s * 272 + rr;
            abase[(bi + ((0 ^ aC4) * 68)) * 2 + h] = f2tf(ra[u].x);
            abase[(bi + ((1 ^ aC4) * 68)) * 2 + h] = f2tf(ra[u].y);
            abase[(bi + ((2 ^ aC4) * 68)) * 2 + h] = f2tf(ra[u].z);
            abase[(bi + ((3 ^ aC4) * 68)) * 2 + h] = f2tf(ra[u].w);
        }
#pragma unroll
        for (int u = 0; u < 2; u++) {
            int k = bK0 + u * 8;
            unsigned* p = &Bs[st][k][bC4 * 4];
            p[0] = f2tf(rb[u].x); p[1] = f2tf(rb[u].y);
            p[2] = f2tf(rb[u].z); p[3] = f2tf(rb[u].w);
        }
    };

    float acc[2][8][4];
#pragma unroll
    for (int i = 0; i < 2; i++)
#pragma unroll
        for (int j = 0; j < 8; j++)
#pragma unroll
            for (int c = 0; c < 4; c++) acc[i][j][c] = 0.f;

    const int mbase = warpRow * 32;
    const int nbase = warpCol * 64;
    const int rrb0  = warpRow * 16 + qr;       // rr for i=0 (= (wr*2+0)*8 + qr)

    loadA(0, aReg); loadB(0, bReg);
    stage(0, aReg, bReg);
    __syncthreads();

    const int stages = K >> 4;
    for (int s = 0; s < stages; s++) {
        const int cur = s & 1;
        if (s + 1 < stages) { loadA((s + 1) << 4, aReg); loadB((s + 1) << 4, bReg); }

#pragma unroll
        for (int kk = 0; kk < 16; kk += 8) {
            const int kkb = kk >> 3;
            unsigned a[2][4], b[8][2];
#pragma unroll
            for (int i = 0; i < 2; i++) {
                int rr = rrb0 + i * 8;
                // s=0 pair -> (a0, a1); s=1 pair -> (a2, a3)
                uint2 p0 = Apair[cur][kkb * 544 + 0 * 272 + ((qk ^ (kkb * 2 + 0)) * 68) + rr];
                uint2 p1 = Apair[cur][kkb * 544 + 1 * 272 + ((qk ^ (kkb * 2 + 1)) * 68) + rr];
                a[i][0] = p0.x; a[i][1] = p0.y;
                a[i][2] = p1.x; a[i][3] = p1.y;
            }
#pragma unroll
            for (int j = 0; j < 8; j++) {
                int c = nbase + j * 8 + qr;
                b[j][0] = Bs[cur][kk + qk][c];
                b[j][1] = Bs[cur][kk + 4 + qk][c];
            }
#pragma unroll
            for (int i = 0; i < 2; i++)
#pragma unroll
                for (int j = 0; j < 8; j++) {
                    asm volatile(
                        "mma.sync.aligned.m16n8k8.row.col.f32.tf32.tf32.f32 "
                        "{%0,%1,%2,%3}, {%4,%5,%6,%7}, {%8,%9}, {%0,%1,%2,%3};"
                        : "+f"(acc[i][j][0]), "+f"(acc[i][j][1]),
                          "+f"(acc[i][j][2]), "+f"(acc[i][j][3])
                        : "r"(a[i][0]), "r"(a[i][1]), "r"(a[i][2]), "r"(a[i][3]),
                          "r"(b[j][0]), "r"(b[j][1]));
                }
        }

        if (s + 1 < stages) stage(cur ^ 1, aReg, bReg);
        __syncthreads();
    }

    // epilogue: c0,c1 at (qr, 2qk), c2,c3 at (qr+8, 2qk) within each 16x8 tile
#pragma unroll
    for (int i = 0; i < 2; i++) {
#pragma unroll
        for (int h = 0; h < 2; h++) {   // h=0: rows qr, h=1: rows qr+8
            int r = row0 + mbase + i * 16 + qr + h * 8;
            if (r >= M) continue;
            if (SCATTER) {
                int target = sidx[r];
                float* Crow = C + (size_t)target * ldc;
#pragma unroll
                for (int j = 0; j < 8; j++) {
                    int c = col0 + nbase + j * 8 + 2 * qk;
                    float v0 = acc[i][j][h * 2 + 0] + bias[c];
                    float v1 = acc[i][j][h * 2 + 1] + bias[c + 1];
                    if (RELU) { v0 = fmaxf(v0, 0.f); v1 = fmaxf(v1, 0.f); }
                    asm volatile("red.global.add.v2.f32 [%0], {%1, %2};"
                                 :: "l"(Crow + c), "f"(v0), "f"(v1) : "memory");
                }
            } else {
                float* Crow = C + (size_t)r * ldc;
#pragma unroll
                for (int j = 0; j < 8; j++) {
                    int c = col0 + nbase + j * 8 + 2 * qk;
                    float v0 = acc[i][j][h * 2 + 0] + (bias ? bias[c] : 0.f);
                    float v1 = acc[i][j][h * 2 + 1] + (bias ? bias[c + 1] : 0.f);
                    if (RELU) { v0 = fmaxf(v0, 0.f); v1 = fmaxf(v1, 0.f); }
                    *(float2*)(Crow + c) = make_float2(v0, v1);
                }
            }
        }
    }
}

// ---------------------------------------------------------------------------
// hidden1[e, :] = relu( Pa[dst[e]] + Pb[src[e]] + ebuf[e]·Wc + b1 )
// ---------------------------------------------------------------------------
#define ET 16
__global__ __launch_bounds__(256) void hidden1_kernel(
    const float* __restrict__ P,    // [N, 512] = [Pa | Pb]
    const float* __restrict__ Ebuf, // [E, 32]
    const float* __restrict__ Wc,   // [32, 256]
    const float* __restrict__ b1,   // [256]
    const int* __restrict__ src,
    const int* __restrict__ dst,
    float* __restrict__ out,        // [E, 256]
    int E)
{
    const int j = threadIdx.x;
    const int e0 = blockIdx.x * ET;
    __shared__ float esm[ET][32];
    __shared__ int sdst[ET], ssrc[ET];

    float wc[32];
#pragma unroll
    for (int k = 0; k < 32; k++) wc[k] = Wc[k * 256 + j];

    const int ne = min(ET, E - e0);
    if (j < ne) {
        sdst[j] = dst[e0 + j];
        ssrc[j] = src[e0 + j];
    }
    for (int t = j; t < ne * 32; t += 256)
        esm[t >> 5][t & 31] = Ebuf[(size_t)e0 * 32 + t];
    __syncthreads();

    const float bj = b1[j];
    for (int i = 0; i < ne; i++) {
        float acc = bj + P[(size_t)sdst[i] * 512 + j]
                       + P[(size_t)ssrc[i] * 512 + 256 + j];
#pragma unroll
        for (int k = 0; k < 32; k++) acc = fmaf(esm[i][k], wc[k], acc);
        out[(size_t)(e0 + i) * 256 + j] = fmaxf(acc, 0.f);
    }
}

// ---------------------------------------------------------------------------
__global__ __launch_bounds__(256) void edge_proj(
    const float* __restrict__ ea, const float* __restrict__ W,
    const float* __restrict__ b, float* __restrict__ out, int E)
{
    __shared__ float Ws[1024];
    __shared__ float es[8][32];
    const int t = threadIdx.x;
    for (int i = t; i < 1024; i += 256) Ws[i] = W[i];
    const int e0 = blockIdx.x * 8;
    const int ne = min(8, E - e0);
    for (int i = t; i < ne * 32; i += 256)
        es[i >> 5][i & 31] = ea[(size_t)e0 * 32 + i];
    __syncthreads();
    const int el = t >> 5, c = t & 31;
    if (el < ne) {
        float acc = b[c];
#pragma unroll
        for (int k = 0; k < 32; k++) acc = fmaf(es[el][k], Ws[k * 32 + c], acc);
        out[(size_t)(e0 + el) * 32 + c] = acc;
    }
}

__global__ void zero_aggr(float* __restrict__ Hcat, int N)
{
    int idx = blockIdx.x * blockDim.x + threadIdx.x;
    if (idx < N * 64) {
        int r = idx >> 6, c = (idx & 63) << 2;
        *(float4*)(Hcat + (size_t)r * 512 + 256 + c) = make_float4(0.f, 0.f, 0.f, 0.f);
    }
}

__global__ void head2(const float* __restrict__ T, const float* __restrict__ w2,
                      const float* __restrict__ b2, float* __restrict__ out, int N)
{
    int gw = (blockIdx.x * blockDim.x + threadIdx.x) >> 5;
    int lane = threadIdx.x & 31;
    if (gw >= N) return;
    const float* row = T + (size_t)gw * 128;
    float s = 0.f;
#pragma unroll
    for (int k = lane; k < 128; k += 32) s = fmaf(row[k], w2[k], s);
#pragma unroll
    for (int o = 16; o; o >>= 1) s += __shfl_xor_sync(0xFFFFFFFFu, s, o);
    if (lane == 0) out[gw] = s + b2[0];
}

__global__ void copy_h(const float* __restrict__ Hcat, float* __restrict__ out, int N)
{
    int idx = blockIdx.x * blockDim.x + threadIdx.x;
    if (idx < N * 64) {
        int r = idx >> 6, c = (idx & 63) << 2;
        *(float4*)(out + (size_t)r * 256 + c) =
            *(const float4*)(Hcat + (size_t)r * 512 + c);
    }
}

// ---------------------------------------------------------------------------
extern "C" void kernel_launch(void* const* d_in, const int* in_sizes, int n_in,
                              void* d_out, int out_size)
{
    const float* x       = (const float*)d_in[0];
    const int*   ei      = (const int*)d_in[1];
    const float* ea      = (const float*)d_in[2];
    const float* node_w  = (const float*)d_in[3];
    const float* node_b  = (const float*)d_in[4];
    const float* edge_w  = (const float*)d_in[5];
    const float* edge_b  = (const float*)d_in[6];
    const float* msg_w1  = (const float*)d_in[7];
    const float* msg_b1  = (const float*)d_in[8];
    const float* msg_w2  = (const float*)d_in[9];
    const float* msg_b2  = (const float*)d_in[10];
    const float* up_w1   = (const float*)d_in[11];
    const float* up_b1   = (const float*)d_in[12];
    const float* up_w2   = (const float*)d_in[13];
    const float* up_b2   = (const float*)d_in[14];
    const float* tok_w1  = (const float*)d_in[15];
    const float* tok_b1  = (const float*)d_in[16];
    const float* tok_w2  = (const float*)d_in[17];
    const float* tok_b2  = (const float*)d_in[18];

    const int N = in_sizes[0] / 128;   // 50000
    const int E = in_sizes[2] / 32;    // 400000
    const int* src = ei;               // edge_index[0]
    const int* dst = ei + E;           // edge_index[1]

    float *Hcat, *P, *M1, *U, *Eb, *T;
    cudaGetSymbolAddress((void**)&Hcat, g_Hcat);
    cudaGetSymbolAddress((void**)&P,    g_P);
    cudaGetSymbolAddress((void**)&M1,   g_M1);
    cudaGetSymbolAddress((void**)&U,    g_U);
    cudaGetSymbolAddress((void**)&Eb,   g_E);
    cudaGetSymbolAddress((void**)&T,    g_T);

    float* out_logits = (float*)d_out;
    float* out_h      = out_logits + N;

    const int mbN = (N + 127) / 128;   // 391
    const int mbE = (E + 127) / 128;   // 3125

    // h = x @ node_w + node_b  -> Hcat[:, 0:256]
    tf32gemm<false, false><<<dim3(2, mbN), 256>>>(x, 128, node_w, 256, node_b,
                                                  Hcat, 512, N, 256, 128, nullptr);
    // e = edge_attr @ edge_w + edge_b
    edge_proj<<<(E + 7) / 8, 256>>>(ea, edge_w, edge_b, Eb, E);

    for (int l = 0; l < 3; l++) {
        const float* w1 = msg_w1 + (size_t)l * 544 * 256;
        // Pa = h @ W1[0:256], Pb = h @ W1[256:512]
        tf32gemm<false, false><<<dim3(2, mbN), 256>>>(Hcat, 512, w1, 256, nullptr,
                                                      P, 512, N, 256, 256, nullptr);
        tf32gemm<false, false><<<dim3(2, mbN), 256>>>(Hcat, 512, w1 + 256 * 256, 256, nullptr,
                                                      P + 256, 512, N, 256, 256, nullptr);
        // aggr = 0
        zero_aggr<<<(N * 64 + 255) / 256, 256>>>(Hcat, N);
        // hidden1 = relu(Pa[dst] + Pb[src] + e@Wc + b1)
        hidden1_kernel<<<(E + ET - 1) / ET, 256>>>(P, Eb, w1 + 512 * 256,
                                                   msg_b1 + l * 256, src, dst, M1, E);
        // m = relu(hidden1 @ W2 + b2); aggr[dst] += m   (fused scatter)
        tf32gemm<true, true><<<dim3(2, mbE), 256>>>(M1, 256,
                                                    msg_w2 + (size_t)l * 256 * 256, 256,
                                                    msg_b2 + l * 256,
                                                    Hcat + 256, 512, E, 256, 256, dst);
        // u = relu([h|aggr] @ up_w1 + b1)
        tf32gemm<true, false><<<dim3(2, mbN), 256>>>(Hcat, 512,
                                                     up_w1 + (size_t)l * 512 * 256, 256,
                                                     up_b1 + l * 256,
                                                     U, 256, N, 256, 512, nullptr);
        // h = relu(u @ up_w2 + b2) -> Hcat[:, 0:256]
        tf32gemm<true, false><<<dim3(2, mbN), 256>>>(U, 256,
                                                     up_w2 + (size_t)l * 256 * 256, 256,
                                                     up_b2 + l * 256,
                                                     Hcat, 512, N, 256, 256, nullptr);
    }

    // token head
    tf32gemm<true, false><<<dim3(1, mbN), 256>>>(Hcat, 512, tok_w1, 128, tok_b1,
                                                 T, 128, N, 128, 256, nullptr);
    head2<<<(N * 32 + 255) / 256, 256>>>(T, tok_w2, tok_b2, out_logits, N);
    copy_h<<<(N * 64 + 255) / 256, 256>>>(Hcat, out_h, N);
}

// round 6
// speedup vs baseline: 2.3252x; 1.0775x over previous
#include <cuda_runtime.h>
#include <cstdint>

// ---------------------------------------------------------------------------
// GNN message passing, 50000 nodes / 400000 edges / HIDDEN=256 / 3 layers.
// tf32 mma.sync.m16n8k8 GEMMs with cp.async 3-stage pipelines.
// All tf32 conversions hoisted out of GEMM hot loops (bit-identical):
//   - weights + x pre-converted once per launch
//   - M1 / U / h stored pre-rounded at their producing kernels
// up1 keeps cvt-staging for A (aggr half is atomic-accumulated fp32).
// Segment-sum scatter fused into edge GEMM epilogue (red.global.add.v2.f32).
// ---------------------------------------------------------------------------

#define NN 50000
#define NE 400000

__device__ float g_Hcat[(size_t)NN * 512];   // [h | aggr], h stored tf32-rounded
__device__ float g_P[(size_t)NN * 512];      // [Pa | Pb] (fp32)
__device__ float g_M1[(size_t)NE * 256];     // hidden1 per edge, tf32-rounded
__device__ float g_U[(size_t)NN * 256];      // update hidden, tf32-rounded
__device__ float g_E[(size_t)NE * 32];       // projected edge features
__device__ float g_T[(size_t)NN * 128];      // token head hidden
__device__ float g_Xc[(size_t)NN * 128];     // x, tf32-rounded
__device__ float g_Wc[1269760];              // all weights, tf32-rounded

// g_Wc offsets (floats)
#define WC_MSG1 0                            // 3*544*256 = 417792
#define WC_MSG2 417792                       // 3*256*256 = 196608
#define WC_UP1  614400                       // 3*512*256 = 393216
#define WC_UP2  1007616                      // 3*256*256 = 196608
#define WC_NODE 1204224                      // 128*256   = 32768
#define WC_TOK  1236992                      // 256*128   = 32768

__device__ __forceinline__ unsigned f2tf(float f) {
    unsigned u;
    asm("cvt.rna.tf32.f32 %0, %1;" : "=r"(u) : "f"(f));
    return u;
}
__device__ __forceinline__ float f2tf_f(float f) {
    return __uint_as_float(f2tf(f));
}
__device__ __forceinline__ uint32_t smem_u32(const void* p) {
    return (uint32_t)__cvta_generic_to_shared(p);
}
__device__ __forceinline__ void cp16(uint32_t dst, const void* src) {
    asm volatile("cp.async.cg.shared.global [%0], [%1], 16;" :: "r"(dst), "l"(src));
}
__device__ __forceinline__ void cp_commit() {
    asm volatile("cp.async.commit_group;" ::: "memory");
}

// smem layout (words): A bufs 3*2560 @0, B bufs 3*2176 @7680, bias 128 @14208
#define AW 20
#define ABUF 2560
#define BW 136
#define BBUF 2176
#define BOFF 7680
#define BIASOFF 14208
#define SMEM_BYTES ((BIASOFF + 128) * 4)

// ---------------------------------------------------------------------------
// TF32 GEMM: C[M, gridDim.x*128] = act(A[M,K] @ B[K,N] + bias)
// 128x128 CTA tile, BK=16, 256 threads (8 warps, 32x64 each), 3-stage cp.async.
// PRECVT: A already tf32-rounded -> cp.async staging (rows clamped; epilogue
//         guards). else: LDG-prefetch + cvt + STS (for fp32 A).
// RSTORE: epilogue stores tf32-rounded values.
// SCATTER: red.add.v2 into C[sidx[row]].
// ---------------------------------------------------------------------------
template <bool RELU, bool SCATTER, bool PRECVT, bool RSTORE>
__global__ __launch_bounds__(256, 2) void tf32gemm(
    const float* __restrict__ A, int lda,
    const float* __restrict__ B, int ldb,
    const float* __restrict__ bias,
    float* __restrict__ C, int ldc,
    int M, int K,
    const int* __restrict__ sidx)
{
    extern __shared__ unsigned dynsmem[];

    const int tid  = threadIdx.x;
    const int lane = tid & 31;
    const int wid  = tid >> 5;
    const int warpRow = wid >> 1;
    const int warpCol = wid & 1;
    const int qr = lane >> 2;
    const int qk = lane & 3;

    const int row0 = blockIdx.y * 128;
    const int col0 = blockIdx.x * 128;

    const int aRow = tid >> 2;   // 0..63 (rows aRow, aRow+64)
    const int aC4  = tid & 3;
    const int bK   = tid >> 5;   // 0..7  (rows bK, bK+8)
    const int bC4  = tid & 31;

    float* sbias = (float*)(dynsmem + BIASOFF);
    if (tid < 128) sbias[tid] = bias ? bias[col0 + tid] : 0.f;

    const int nc = K >> 4;

    // ---- staging helpers ----
    auto cpA = [&](int s, int k0) {
        unsigned* buf = dynsmem + (s % 3) * ABUF;
#pragma unroll
        for (int u = 0; u < 2; u++) {
            int row = aRow + u * 64;
            int gr = min(row0 + row, M - 1);
            cp16(smem_u32(&buf[row * AW + aC4 * 4]),
                 A + (size_t)gr * lda + k0 + aC4 * 4);
        }
    };
    auto cpB = [&](int s, int k0) {
        unsigned* buf = dynsmem + BOFF + (s % 3) * BBUF;
#pragma unroll
        for (int u = 0; u < 2; u++) {
            int k = bK + u * 8;
            cp16(smem_u32(&buf[k * BW + bC4 * 4]),
                 B + (size_t)(k0 + k) * ldb + col0 + bC4 * 4);
        }
    };
    float4 aReg[2];
    auto ldgA = [&](int k0) {
#pragma unroll
        for (int u = 0; u < 2; u++) {
            int row = aRow + u * 64;
            if (row0 + row < M)
                aReg[u] = *(const float4*)(A + (size_t)(row0 + row) * lda + k0 + aC4 * 4);
            else
                aReg[u] = make_float4(0.f, 0.f, 0.f, 0.f);
        }
    };
    auto stsA = [&](int s) {
        unsigned* buf = dynsmem + (s % 3) * ABUF;
#pragma unroll
        for (int u = 0; u < 2; u++) {
            int row = aRow + u * 64;
            uint4 w = { f2tf(aReg[u].x), f2tf(aReg[u].y),
                        f2tf(aReg[u].z), f2tf(aReg[u].w) };
            *(uint4*)&buf[row * AW + aC4 * 4] = w;
        }
    };

    // ---- prologue: chunks 0,1 in flight ----
    if (PRECVT) {
        cpA(0, 0);  cpB(0, 0);  cp_commit();
        cpA(1, 16); cpB(1, 16); cp_commit();
    } else {
        ldgA(0); stsA(0);
        cpB(0, 0);  cp_commit();
        cpB(1, 16); cp_commit();
    }

    float acc[2][8][4];
#pragma unroll
    for (int i = 0; i < 2; i++)
#pragma unroll
        for (int j = 0; j < 8; j++)
#pragma unroll
            for (int c = 0; c < 4; c++) acc[i][j][c] = 0.f;

    const int mbase = warpRow * 32;
    const int nbase = warpCol * 64;

    for (int s = 0; s < nc; s++) {
        if (!PRECVT && s + 1 < nc) ldgA((s + 1) << 4);

        if (s + 1 < nc)
            asm volatile("cp.async.wait_group 1;" ::: "memory");
        else
            asm volatile("cp.async.wait_group 0;" ::: "memory");
        __syncthreads();

        if (s + 2 < nc) {
            if (PRECVT) cpA(s + 2, (s + 2) << 4);
            cpB(s + 2, (s + 2) << 4);
            cp_commit();
        }

        const unsigned* As = dynsmem + (s % 3) * ABUF;
        const unsigned* Bs = dynsmem + BOFF + (s % 3) * BBUF;

#pragma unroll
        for (int kk = 0; kk < 16; kk += 8) {
            unsigned a[2][4], b[8][2];
#pragma unroll
            for (int i = 0; i < 2; i++) {
                int r = mbase + i * 16 + qr;
                a[i][0] = As[r * AW + kk + qk];
                a[i][1] = As[(r + 8) * AW + kk + qk];
                a[i][2] = As[r * AW + kk + 4 + qk];
                a[i][3] = As[(r + 8) * AW + kk + 4 + qk];
            }
#pragma unroll
            for (int j = 0; j < 8; j++) {
                int c = nbase + j * 8 + qr;
                b[j][0] = Bs[(kk + qk) * BW + c];
                b[j][1] = Bs[(kk + 4 + qk) * BW + c];
            }
#pragma unroll
            for (int i = 0; i < 2; i++)
#pragma unroll
                for (int j = 0; j < 8; j++) {
                    asm volatile(
                        "mma.sync.aligned.m16n8k8.row.col.f32.tf32.tf32.f32 "
                        "{%0,%1,%2,%3}, {%4,%5,%6,%7}, {%8,%9}, {%0,%1,%2,%3};"
                        : "+f"(acc[i][j][0]), "+f"(acc[i][j][1]),
                          "+f"(acc[i][j][2]), "+f"(acc[i][j][3])
                        : "r"(a[i][0]), "r"(a[i][1]), "r"(a[i][2]), "r"(a[i][3]),
                          "r"(b[j][0]), "r"(b[j][1]));
                }
        }

        if (!PRECVT && s + 1 < nc) stsA(s + 1);
    }

    // ---- epilogue ----
#pragma unroll
    for (int i = 0; i < 2; i++) {
#pragma unroll
        for (int h = 0; h < 2; h++) {
            int r = row0 + mbase + i * 16 + qr + h * 8;
            if (r >= M) continue;
            if (SCATTER) {
                int target = sidx[r];
                float* Crow = C + (size_t)target * ldc;
#pragma unroll
                for (int j = 0; j < 8; j++) {
                    int c = col0 + nbase + j * 8 + 2 * qk;
                    float v0 = acc[i][j][h * 2 + 0] + sbias[c - col0];
                    float v1 = acc[i][j][h * 2 + 1] + sbias[c - col0 + 1];
                    if (RELU) { v0 = fmaxf(v0, 0.f); v1 = fmaxf(v1, 0.f); }
                    asm volatile("red.global.add.v2.f32 [%0], {%1, %2};"
                                 :: "l"(Crow + c), "f"(v0), "f"(v1) : "memory");
                }
            } else {
                float* Crow = C + (size_t)r * ldc;
#pragma unroll
                for (int j = 0; j < 8; j++) {
                    int c = col0 + nbase + j * 8 + 2 * qk;
                    float v0 = acc[i][j][h * 2 + 0] + sbias[c - col0];
                    float v1 = acc[i][j][h * 2 + 1] + sbias[c - col0 + 1];
                    if (RELU) { v0 = fmaxf(v0, 0.f); v1 = fmaxf(v1, 0.f); }
                    if (RSTORE) { v0 = f2tf_f(v0); v1 = f2tf_f(v1); }
                    *(float2*)(Crow + c) = make_float2(v0, v1);
                }
            }
        }
    }
}

// ---------------------------------------------------------------------------
// elementwise tf32 rounding: dst[i] = rna(src[i])  (n % 4 == 0)
// ---------------------------------------------------------------------------
__global__ void cvt_buf(const float* __restrict__ src, float* __restrict__ dst, int n4)
{
    int i = blockIdx.x * blockDim.x + threadIdx.x;
    if (i < n4) {
        float4 v = *(const float4*)(src + i * 4);
        float4 o = { f2tf_f(v.x), f2tf_f(v.y), f2tf_f(v.z), f2tf_f(v.w) };
        *(float4*)(dst + i * 4) = o;
    }
}

// ---------------------------------------------------------------------------
// hidden1[e, :] = rna(relu( Pa[dst[e]] + Pb[src[e]] + ebuf[e]·Wc + b1 ))
// ---------------------------------------------------------------------------
#define ET 16
__global__ __launch_bounds__(256) void hidden1_kernel(
    const float* __restrict__ P,    // [N, 512] = [Pa | Pb]
    const float* __restrict__ Ebuf, // [E, 32]
    const float* __restrict__ Wc,   // [32, 256] (original fp32)
    const float* __restrict__ b1,   // [256]
    const int* __restrict__ src,
    const int* __restrict__ dst,
    float* __restrict__ out,        // [E, 256] tf32-rounded
    int E)
{
    const int j = threadIdx.x;
    const int e0 = blockIdx.x * ET;
    __shared__ float esm[ET][32];
    __shared__ int sdst[ET], ssrc[ET];

    float wc[32];
#pragma unroll
    for (int k = 0; k < 32; k++) wc[k] = Wc[k * 256 + j];

    const int ne = min(ET, E - e0);
    if (j < ne) {
        sdst[j] = dst[e0 + j];
        ssrc[j] = src[e0 + j];
    }
    for (int t = j; t < ne * 32; t += 256)
        esm[t >> 5][t & 31] = Ebuf[(size_t)e0 * 32 + t];
    __syncthreads();

    const float bj = b1[j];
    for (int i = 0; i < ne; i++) {
        float acc = bj + P[(size_t)sdst[i] * 512 + j]
                       + P[(size_t)ssrc[i] * 512 + 256 + j];
#pragma unroll
        for (int k = 0; k < 32; k++) acc = fmaf(esm[i][k], wc[k], acc);
        out[(size_t)(e0 + i) * 256 + j] = f2tf_f(fmaxf(acc, 0.f));
    }
}

// ---------------------------------------------------------------------------
__global__ __launch_bounds__(256) void edge_proj(
    const float* __restrict__ ea, const float* __restrict__ W,
    const float* __restrict__ b, float* __restrict__ out, int E)
{
    __shared__ float Ws[1024];
    __shared__ float es[8][32];
    const int t = threadIdx.x;
    for (int i = t; i < 1024; i += 256) Ws[i] = W[i];
    const int e0 = blockIdx.x * 8;
    const int ne = min(8, E - e0);
    for (int i = t; i < ne * 32; i += 256)
        es[i >> 5][i & 31] = ea[(size_t)e0 * 32 + i];
    __syncthreads();
    const int el = t >> 5, c = t & 31;
    if (el < ne) {
        float acc = b[c];
#pragma unroll
        for (int k = 0; k < 32; k++) acc = fmaf(es[el][k], Ws[k * 32 + c], acc);
        out[(size_t)(e0 + el) * 32 + c] = acc;
    }
}

__global__ void zero_aggr(float* __restrict__ Hcat, int N)
{
    int idx = blockIdx.x * blockDim.x + threadIdx.x;
    if (idx < N * 64) {
        int r = idx >> 6, c = (idx & 63) << 2;
        *(float4*)(Hcat + (size_t)r * 512 + 256 + c) = make_float4(0.f, 0.f, 0.f, 0.f);
    }
}

__global__ void head2(const float* __restrict__ T, const float* __restrict__ w2,
                      const float* __restrict__ b2, float* __restrict__ out, int N)
{
    int gw = (blockIdx.x * blockDim.x + threadIdx.x) >> 5;
    int lane = threadIdx.x & 31;
    if (gw >= N) return;
    const float* row = T + (size_t)gw * 128;
    float s = 0.f;
#pragma unroll
    for (int k = lane; k < 128; k += 32) s = fmaf(row[k], w2[k], s);
#pragma unroll
    for (int o = 16; o; o >>= 1) s += __shfl_xor_sync(0xFFFFFFFFu, s, o);
    if (lane == 0) out[gw] = s + b2[0];
}

__global__ void copy_h(const float* __restrict__ Hcat, float* __restrict__ out, int N)
{
    int idx = blockIdx.x * blockDim.x + threadIdx.x;
    if (idx < N * 64) {
        int r = idx >> 6, c = (idx & 63) << 2;
        *(float4*)(out + (size_t)r * 256 + c) =
            *(const float4*)(Hcat + (size_t)r * 512 + c);
    }
}

// ---------------------------------------------------------------------------
extern "C" void kernel_launch(void* const* d_in, const int* in_sizes, int n_in,
                              void* d_out, int out_size)
{
    const float* x       = (const float*)d_in[0];
    const int*   ei      = (const int*)d_in[1];
    const float* ea      = (const float*)d_in[2];
    const float* node_w  = (const float*)d_in[3];
    const float* node_b  = (const float*)d_in[4];
    const float* edge_w  = (const float*)d_in[5];
    const float* edge_b  = (const float*)d_in[6];
    const float* msg_w1  = (const float*)d_in[7];
    const float* msg_b1  = (const float*)d_in[8];
    const float* msg_w2  = (const float*)d_in[9];
    const float* msg_b2  = (const float*)d_in[10];
    const float* up_w1   = (const float*)d_in[11];
    const float* up_b1   = (const float*)d_in[12];
    const float* up_w2   = (const float*)d_in[13];
    const float* up_b2   = (const float*)d_in[14];
    const float* tok_w1  = (const float*)d_in[15];
    const float* tok_b1  = (const float*)d_in[16];
    const float* tok_w2  = (const float*)d_in[17];
    const float* tok_b2  = (const float*)d_in[18];

    const int N = in_sizes[0] / 128;   // 50000
    const int E = in_sizes[2] / 32;    // 400000
    const int* src = ei;               // edge_index[0]
    const int* dst = ei + E;           // edge_index[1]

    float *Hcat, *P, *M1, *U, *Eb, *T, *Xc, *Wc;
    cudaGetSymbolAddress((void**)&Hcat, g_Hcat);
    cudaGetSymbolAddress((void**)&P,    g_P);
    cudaGetSymbolAddress((void**)&M1,   g_M1);
    cudaGetSymbolAddress((void**)&U,    g_U);
    cudaGetSymbolAddress((void**)&Eb,   g_E);
    cudaGetSymbolAddress((void**)&T,    g_T);
    cudaGetSymbolAddress((void**)&Xc,   g_Xc);
    cudaGetSymbolAddress((void**)&Wc,   g_Wc);

    float* out_logits = (float*)d_out;
    float* out_h      = out_logits + N;

    const int mbN = (N + 127) / 128;   // 391
    const int mbE = (E + 127) / 128;   // 3125

    // opt into >48KB dynamic smem for all GEMM instantiations
    cudaFuncSetAttribute(tf32gemm<false, false, true,  true >, cudaFuncAttributeMaxDynamicSharedMemorySize, SMEM_BYTES);
    cudaFuncSetAttribute(tf32gemm<false, false, true,  false>, cudaFuncAttributeMaxDynamicSharedMemorySize, SMEM_BYTES);
    cudaFuncSetAttribute(tf32gemm<true,  true,  true,  false>, cudaFuncAttributeMaxDynamicSharedMemorySize, SMEM_BYTES);
    cudaFuncSetAttribute(tf32gemm<true,  false, false, true >, cudaFuncAttributeMaxDynamicSharedMemorySize, SMEM_BYTES);
    cudaFuncSetAttribute(tf32gemm<true,  false, true,  true >, cudaFuncAttributeMaxDynamicSharedMemorySize, SMEM_BYTES);
    cudaFuncSetAttribute(tf32gemm<true,  false, true,  false>, cudaFuncAttributeMaxDynamicSharedMemorySize, SMEM_BYTES);

    // ---- pre-convert weights + x to tf32 (bit-identical to staging cvt) ----
    cvt_buf<<<(3 * 544 * 256 / 4 + 255) / 256, 256>>>(msg_w1, Wc + WC_MSG1, 3 * 544 * 256 / 4);
    cvt_buf<<<(3 * 256 * 256 / 4 + 255) / 256, 256>>>(msg_w2, Wc + WC_MSG2, 3 * 256 * 256 / 4);
    cvt_buf<<<(3 * 512 * 256 / 4 + 255) / 256, 256>>>(up_w1,  Wc + WC_UP1,  3 * 512 * 256 / 4);
    cvt_buf<<<(3 * 256 * 256 / 4 + 255) / 256, 256>>>(up_w2,  Wc + WC_UP2,  3 * 256 * 256 / 4);
    cvt_buf<<<(128 * 256 / 4 + 255) / 256, 256>>>(node_w, Wc + WC_NODE, 128 * 256 / 4);
    cvt_buf<<<(256 * 128 / 4 + 255) / 256, 256>>>(tok_w1, Wc + WC_TOK,  256 * 128 / 4);
    cvt_buf<<<(NN * 128 / 4 + 255) / 256, 256>>>(x, Xc, NN * 128 / 4);

    // h = x @ node_w + node_b -> Hcat[:, 0:256] (stored rounded)
    tf32gemm<false, false, true, true><<<dim3(2, mbN), 256, SMEM_BYTES>>>(
        Xc, 128, Wc + WC_NODE, 256, node_b, Hcat, 512, N, 128, nullptr);
    // e = edge_attr @ edge_w + edge_b
    edge_proj<<<(E + 7) / 8, 256>>>(ea, edge_w, edge_b, Eb, E);

    for (int l = 0; l < 3; l++) {
        const float* w1c = Wc + WC_MSG1 + (size_t)l * 544 * 256;
        // Pa = h @ W1[0:256], Pb = h @ W1[256:512]  (P stored fp32)
        tf32gemm<false, false, true, false><<<dim3(2, mbN), 256, SMEM_BYTES>>>(
            Hcat, 512, w1c, 256, nullptr, P, 512, N, 256, nullptr);
        tf32gemm<false, false, true, false><<<dim3(2, mbN), 256, SMEM_BYTES>>>(
            Hcat, 512, w1c + 256 * 256, 256, nullptr, P + 256, 512, N, 256, nullptr);
        // aggr = 0
        zero_aggr<<<(N * 64 + 255) / 256, 256>>>(Hcat, N);
        // hidden1 = rna(relu(Pa[dst] + Pb[src] + e@Wc + b1)) -> M1
        hidden1_kernel<<<(E + ET - 1) / ET, 256>>>(
            P, Eb, msg_w1 + (size_t)l * 544 * 256 + 512 * 256,
            msg_b1 + l * 256, src, dst, M1, E);
        // m = relu(M1 @ W2 + b2); aggr[dst] += m  (fused scatter)
        tf32gemm<true, true, true, false><<<dim3(2, mbE), 256, SMEM_BYTES>>>(
            M1, 256, Wc + WC_MSG2 + (size_t)l * 256 * 256, 256,
            msg_b2 + l * 256, Hcat + 256, 512, E, 256, dst);
        // u = relu([h|aggr] @ up_w1 + b1)  (A cvt-staged; U stored rounded)
        tf32gemm<true, false, false, true><<<dim3(2, mbN), 256, SMEM_BYTES>>>(
            Hcat, 512, Wc + WC_UP1 + (size_t)l * 512 * 256, 256,
            up_b1 + l * 256, U, 256, N, 512, nullptr);
        // h = relu(u @ up_w2 + b2) -> Hcat[:, 0:256] (stored rounded)
        tf32gemm<true, false, true, true><<<dim3(2, mbN), 256, SMEM_BYTES>>>(
            U, 256, Wc + WC_UP2 + (size_t)l * 256 * 256, 256,
            up_b2 + l * 256, Hcat, 512, N, 256, nullptr);
    }

    // token head
    tf32gemm<true, false, true, false><<<dim3(1, mbN), 256, SMEM_BYTES>>>(
        Hcat, 512, Wc + WC_TOK, 128, tok_b1, T, 128, N, 256, nullptr);
    head2<<<(N * 32 + 255) / 256, 256>>>(T, tok_w2, tok_b2, out_logits, N);
    copy_h<<<(N * 64 + 255) / 256, 256>>>(Hcat, out_h, N);
}